// round 4
// baseline (speedup 1.0000x reference)
#include <cuda_runtime.h>
#include <cstdint>

// UpSmpl_3066606649708 — fused conv3d(64->256, 3x3x3, pad1) + pixel-shuffle x2
// + skip-add, direct-conv with packed f32x2 FMA (FFMA2) and cp.async pipeline.
//
// x:   (1, 64, 17, 128, 128) f32
// W:   (256, 64, 3, 3, 3)    f32
// b:   (256,)                f32
// out: (1, 32, 33, 256, 256) f32

#define ICN 64
#define ZD  17
#define NTHREADS 256
#define TYH 8          // y rows per block
#define TXW 32         // x cols per block
#define OCB 64         // output channels per block

#define XSLAB (3*10*34)   // 1020 floats: 3 z x 10 y x 34 x
#define WSLAB (27*64)     // 1728 floats: 27 taps x 64 oc

__device__ __forceinline__ unsigned long long pack2(float lo, float hi) {
    unsigned long long r;
    asm("mov.b64 %0, {%1,%2};" : "=l"(r) : "f"(lo), "f"(hi));
    return r;
}
__device__ __forceinline__ void unpack2(unsigned long long v, float& lo, float& hi) {
    asm("mov.b64 {%0,%1}, %2;" : "=f"(lo), "=f"(hi) : "l"(v));
}
__device__ __forceinline__ unsigned long long ffma2(unsigned long long a,
                                                    unsigned long long b,
                                                    unsigned long long c) {
    unsigned long long d;
    asm("fma.rn.f32x2 %0, %1, %2, %3;" : "=l"(d) : "l"(a), "l"(b), "l"(c));
    return d;
}
__device__ __forceinline__ void cpa4(uint32_t dst, const void* src, int bytes) {
    asm volatile("cp.async.ca.shared.global [%0], [%1], 4, %2;"
                 :: "r"(dst), "l"(src), "r"(bytes));
}

__global__ void __launch_bounds__(NTHREADS)
upsmpl_kernel(const float* __restrict__ xin, const float* __restrict__ win,
              const float* __restrict__ bin, float* __restrict__ outp)
{
    __shared__ __align__(16) float sx[2][XSLAB];
    __shared__ __align__(16) float sw[2][WSLAB];

    const int tid  = threadIdx.x;
    const int lane = tid & 31;
    const int og   = tid >> 5;              // 0..7: oc group (8 oc each)

    const int xt     = blockIdx.x;           // 0..3
    const int yt     = blockIdx.y;           // 0..15
    const int z      = blockIdx.z >> 2;      // 0..16
    const int oct    = blockIdx.z & 3;       // 0..3
    const int ocbase = oct * OCB;

    const int gx0 = xt * TXW;
    const int gy0 = yt * TYH;

    auto prefetch = [&](int ic, int s) {
        uint32_t sx_base = (uint32_t)__cvta_generic_to_shared(&sx[s][0]);
        uint32_t sw_base = (uint32_t)__cvta_generic_to_shared(&sw[s][0]);
        // x slab: z in {z-1,z,z+1}, y in [gy0-1, gy0+8], x in [gx0-1, gx0+32]
        for (int l = tid; l < XSLAB; l += NTHREADS) {
            int kz  = l / 340;
            int rem = l - kz * 340;
            int row = rem / 34;
            int col = rem - row * 34;
            int zs = z - 1 + kz;
            int ys = gy0 - 1 + row;
            int xs = gx0 - 1 + col;
            bool ok = ((unsigned)zs < 17u) & ((unsigned)ys < 128u) & ((unsigned)xs < 128u);
            long idx = ((long)(ic * 17 + (ok ? zs : 0)) * 128 + (ok ? ys : 0)) * 128
                       + (ok ? xs : 0);
            cpa4(sx_base + (uint32_t)l * 4u, xin + idx, ok ? 4 : 0);
        }
        // W slab: smem layout [tap][oc], oc contiguous (pairs feed FFMA2 via LDS.64)
        for (int l = tid; l < WSLAB; l += NTHREADS) {
            int oci = l / 27;
            int tap = l - oci * 27;
            const float* src = win + ((long)(ocbase + oci) * 64 + ic) * 27 + tap;
            cpa4(sw_base + (uint32_t)(tap * 64 + oci) * 4u, src, 4);
        }
    };

    unsigned long long acc[TYH][4];
    #pragma unroll
    for (int r = 0; r < TYH; ++r)
        #pragma unroll
        for (int j = 0; j < 4; ++j) acc[r][j] = 0ull;

    prefetch(0, 0);
    asm volatile("cp.async.commit_group;");

    for (int ic = 0; ic < ICN; ++ic) {
        const int cur = ic & 1;
        if (ic + 1 < ICN) {
            prefetch(ic + 1, cur ^ 1);
            asm volatile("cp.async.commit_group;");
            asm volatile("cp.async.wait_group 1;");
        } else {
            asm volatile("cp.async.wait_group 0;");
        }
        __syncthreads();

        const float* sxp = sx[cur];
        const float* swp = sw[cur];

        #pragma unroll
        for (int kz = 0; kz < 3; ++kz) {
            #pragma unroll
            for (int kx = 0; kx < 3; ++kx) {
                // cache 10 x values (rows 0..9) for this (kz, kx); reuse across ky
                unsigned long long xp[10];
                #pragma unroll
                for (int r = 0; r < 10; ++r) {
                    float v = sxp[kz * 340 + r * 34 + lane + kx];
                    xp[r] = pack2(v, v);
                }
                #pragma unroll
                for (int ky = 0; ky < 3; ++ky) {
                    const int tap = (kz * 3 + ky) * 3 + kx;
                    const unsigned long long* wq =
                        (const unsigned long long*)(swp + tap * 64 + og * 8);
                    unsigned long long w0 = wq[0], w1 = wq[1], w2 = wq[2], w3 = wq[3];
                    #pragma unroll
                    for (int r = 0; r < TYH; ++r) {
                        unsigned long long xv = xp[r + ky];
                        acc[r][0] = ffma2(xv, w0, acc[r][0]);
                        acc[r][1] = ffma2(xv, w1, acc[r][1]);
                        acc[r][2] = ffma2(xv, w2, acc[r][2]);
                        acc[r][3] = ffma2(xv, w3, acc[r][3]);
                    }
                }
            }
        }
        __syncthreads();
    }

    // Epilogue: bias + pixel-shuffle scatter + repeated-channel skip add.
    const int xg = gx0 + lane;
    #pragma unroll
    for (int r = 0; r < TYH; ++r) {
        const int yg = gy0 + r;
        #pragma unroll
        for (int j = 0; j < 4; ++j) {
            float v0, v1;
            unpack2(acc[r][j], v0, v1);
            #pragma unroll
            for (int h = 0; h < 2; ++h) {
                const float v = h ? v1 : v0;
                const int oc = ocbase + og * 8 + j * 2 + h;
                int n, p, q, F, sic;
                if (z == 0) {
                    // r1=1 shuffle on frame 0: oc = p*128 + q*64 + n64; keep n64<32
                    if (oc & 32) continue;
                    n = oc & 31;
                    q = (oc >> 6) & 1;
                    p = oc >> 7;
                    F = 0;
                    sic = (p * 64 + q * 32 + n) >> 1;   // repeat(x, 2) channel map
                } else {
                    // r1=2 shuffle on frames 1..16: oc = a*128 + p*64 + q*32 + n
                    n = oc & 31;
                    q = (oc >> 5) & 1;
                    p = (oc >> 6) & 1;
                    const int a = oc >> 7;
                    F = 2 * z - 1 + a;
                    sic = oc >> 2;                      // repeat(x, 4) channel map
                }
                const float skip = xin[((long)(sic * 17 + z) * 128 + yg) * 128 + xg];
                const float val  = v + bin[oc] + skip;
                const int Y = 2 * yg + p;
                const int X = 2 * xg + q;
                outp[((long)(n * 33 + F) * 256 + Y) * 256 + X] = val;
            }
        }
    }
}

extern "C" void kernel_launch(void* const* d_in, const int* in_sizes, int n_in,
                              void* d_out, int out_size) {
    const float* x = (const float*)d_in[0];
    const float* W = (const float*)d_in[1];
    const float* b = (const float*)d_in[2];
    float* out = (float*)d_out;
    dim3 grid(4, 16, 17 * 4);   // x-tiles, y-tiles, z * oc-tiles
    upsmpl_kernel<<<grid, NTHREADS>>>(x, W, b, out);
}

// round 5
// speedup vs baseline: 1.0010x; 1.0010x over previous
#include <cuda_runtime.h>
#include <cstdint>

// UpSmpl_3066606649708 — fused conv3d(64->256, 3x3x3, pad1) + pixel-shuffle x2
// + skip-add, direct-conv with packed f32x2 FMA (FFMA2) and cp.async pipeline.
//
// x:   (1, 64, 17, 128, 128) f32
// W:   (256, 64, 3, 3, 3)    f32
// b:   (256,)                f32
// out: (1, 32, 33, 256, 256) f32

#define ICN 64
#define ZD  17
#define NTHREADS 256
#define TYH 8          // y rows per block
#define TXW 32         // x cols per block
#define OCB 64         // output channels per block

#define XSLAB (3*10*34)   // 1020 floats: 3 z x 10 y x 34 x
#define WSLAB (27*64)     // 1728 floats: 27 taps x 64 oc

__device__ __forceinline__ unsigned long long pack2(float lo, float hi) {
    unsigned long long r;
    asm("mov.b64 %0, {%1,%2};" : "=l"(r) : "f"(lo), "f"(hi));
    return r;
}
__device__ __forceinline__ void unpack2(unsigned long long v, float& lo, float& hi) {
    asm("mov.b64 {%0,%1}, %2;" : "=f"(lo), "=f"(hi) : "l"(v));
}
__device__ __forceinline__ unsigned long long ffma2(unsigned long long a,
                                                    unsigned long long b,
                                                    unsigned long long c) {
    unsigned long long d;
    asm("fma.rn.f32x2 %0, %1, %2, %3;" : "=l"(d) : "l"(a), "l"(b), "l"(c));
    return d;
}
__device__ __forceinline__ void cpa4(uint32_t dst, const void* src, int bytes) {
    asm volatile("cp.async.ca.shared.global [%0], [%1], 4, %2;"
                 :: "r"(dst), "l"(src), "r"(bytes));
}

__global__ void __launch_bounds__(NTHREADS)
upsmpl_kernel(const float* __restrict__ xin, const float* __restrict__ win,
              const float* __restrict__ bin, float* __restrict__ outp)
{
    __shared__ __align__(16) float sx[2][XSLAB];
    __shared__ __align__(16) float sw[2][WSLAB];

    const int tid  = threadIdx.x;
    const int lane = tid & 31;
    const int og   = tid >> 5;              // 0..7: oc group (8 oc each)

    const int xt     = blockIdx.x;           // 0..3
    const int yt     = blockIdx.y;           // 0..15
    const int z      = blockIdx.z >> 2;      // 0..16
    const int oct    = blockIdx.z & 3;       // 0..3
    const int ocbase = oct * OCB;

    const int gx0 = xt * TXW;
    const int gy0 = yt * TYH;

    auto prefetch = [&](int ic, int s) {
        uint32_t sx_base = (uint32_t)__cvta_generic_to_shared(&sx[s][0]);
        uint32_t sw_base = (uint32_t)__cvta_generic_to_shared(&sw[s][0]);
        // x slab: z in {z-1,z,z+1}, y in [gy0-1, gy0+8], x in [gx0-1, gx0+32]
        for (int l = tid; l < XSLAB; l += NTHREADS) {
            int kz  = l / 340;
            int rem = l - kz * 340;
            int row = rem / 34;
            int col = rem - row * 34;
            int zs = z - 1 + kz;
            int ys = gy0 - 1 + row;
            int xs = gx0 - 1 + col;
            bool ok = ((unsigned)zs < 17u) & ((unsigned)ys < 128u) & ((unsigned)xs < 128u);
            long idx = ((long)(ic * 17 + (ok ? zs : 0)) * 128 + (ok ? ys : 0)) * 128
                       + (ok ? xs : 0);
            cpa4(sx_base + (uint32_t)l * 4u, xin + idx, ok ? 4 : 0);
        }
        // W slab: smem layout [tap][oc], oc contiguous (pairs feed FFMA2 via LDS.64)
        for (int l = tid; l < WSLAB; l += NTHREADS) {
            int oci = l / 27;
            int tap = l - oci * 27;
            const float* src = win + ((long)(ocbase + oci) * 64 + ic) * 27 + tap;
            cpa4(sw_base + (uint32_t)(tap * 64 + oci) * 4u, src, 4);
        }
    };

    unsigned long long acc[TYH][4];
    #pragma unroll
    for (int r = 0; r < TYH; ++r)
        #pragma unroll
        for (int j = 0; j < 4; ++j) acc[r][j] = 0ull;

    prefetch(0, 0);
    asm volatile("cp.async.commit_group;");

    for (int ic = 0; ic < ICN; ++ic) {
        const int cur = ic & 1;
        if (ic + 1 < ICN) {
            prefetch(ic + 1, cur ^ 1);
            asm volatile("cp.async.commit_group;");
            asm volatile("cp.async.wait_group 1;");
        } else {
            asm volatile("cp.async.wait_group 0;");
        }
        __syncthreads();

        const float* sxp = sx[cur];
        const float* swp = sw[cur];

        #pragma unroll
        for (int kz = 0; kz < 3; ++kz) {
            #pragma unroll
            for (int kx = 0; kx < 3; ++kx) {
                // cache 10 x values (rows 0..9) for this (kz, kx); reuse across ky
                unsigned long long xp[10];
                #pragma unroll
                for (int r = 0; r < 10; ++r) {
                    float v = sxp[kz * 340 + r * 34 + lane + kx];
                    xp[r] = pack2(v, v);
                }
                #pragma unroll
                for (int ky = 0; ky < 3; ++ky) {
                    const int tap = (kz * 3 + ky) * 3 + kx;
                    const unsigned long long* wq =
                        (const unsigned long long*)(swp + tap * 64 + og * 8);
                    unsigned long long w0 = wq[0], w1 = wq[1], w2 = wq[2], w3 = wq[3];
                    #pragma unroll
                    for (int r = 0; r < TYH; ++r) {
                        unsigned long long xv = xp[r + ky];
                        acc[r][0] = ffma2(xv, w0, acc[r][0]);
                        acc[r][1] = ffma2(xv, w1, acc[r][1]);
                        acc[r][2] = ffma2(xv, w2, acc[r][2]);
                        acc[r][3] = ffma2(xv, w3, acc[r][3]);
                    }
                }
            }
        }
        __syncthreads();
    }

    // Epilogue: bias + pixel-shuffle scatter + repeated-channel skip add.
    const int xg = gx0 + lane;
    #pragma unroll
    for (int r = 0; r < TYH; ++r) {
        const int yg = gy0 + r;
        #pragma unroll
        for (int j = 0; j < 4; ++j) {
            float v0, v1;
            unpack2(acc[r][j], v0, v1);
            #pragma unroll
            for (int h = 0; h < 2; ++h) {
                const float v = h ? v1 : v0;
                const int oc = ocbase + og * 8 + j * 2 + h;
                int n, p, q, F, sic;
                if (z == 0) {
                    // r1=1 shuffle on frame 0: oc = p*128 + q*64 + n64; keep n64<32
                    if (oc & 32) continue;
                    n = oc & 31;
                    q = (oc >> 6) & 1;
                    p = oc >> 7;
                    F = 0;
                    sic = (p * 64 + q * 32 + n) >> 1;   // repeat(x, 2) channel map
                } else {
                    // r1=2 shuffle on frames 1..16: oc = a*128 + p*64 + q*32 + n
                    n = oc & 31;
                    q = (oc >> 5) & 1;
                    p = (oc >> 6) & 1;
                    const int a = oc >> 7;
                    F = 2 * z - 1 + a;
                    sic = oc >> 2;                      // repeat(x, 4) channel map
                }
                const float skip = xin[((long)(sic * 17 + z) * 128 + yg) * 128 + xg];
                const float val  = v + bin[oc] + skip;
                const int Y = 2 * yg + p;
                const int X = 2 * xg + q;
                outp[((long)(n * 33 + F) * 256 + Y) * 256 + X] = val;
            }
        }
    }
}

extern "C" void kernel_launch(void* const* d_in, const int* in_sizes, int n_in,
                              void* d_out, int out_size) {
    const float* x = (const float*)d_in[0];
    const float* W = (const float*)d_in[1];
    const float* b = (const float*)d_in[2];
    float* out = (float*)d_out;
    dim3 grid(4, 16, 17 * 4);   // x-tiles, y-tiles, z * oc-tiles
    upsmpl_kernel<<<grid, NTHREADS>>>(x, W, b, out);
}

// round 8
// speedup vs baseline: 4.0981x; 4.0941x over previous
#include <cuda_runtime.h>
#include <cstdint>

// UpSmpl — conv3d(64->256,3x3x3,pad1) + pixel-shuffle x2 + skip,
// via warp-level mma.sync m16n8k8 tf32 (compute_103 baseline; no tcgen05).
// x: (1,64,17,128,128) f32   W: (256,64,3,3,3) f32   b: (256,) f32
// out: (1,32,33,256,256) f32

#define ZP 19
#define YP 130
#define XPD 130
#define ICN 64
#define NTAP 27
#define NOC 256

__device__ __align__(256) float g_xT[(size_t)ZP * YP * XPD * ICN]; // padded, tf32-rounded, [z][y][x][ic]
__device__ __align__(256) float g_Wt[(size_t)NTAP * NOC * ICN];    // tf32-rounded, [tap][oc][ic]

#define APITCH 36
#define BPITCH 36
#define ABUF (130 * APITCH)    // 4680 floats
#define BBUF (128 * BPITCH)    // 4608 floats
#define SMEM_FLOATS (3 * ABUF + 3 * BBUF)
#define SMEM_BYTES  (SMEM_FLOATS * 4)

// ---------------- PTX helpers ----------------
__device__ __forceinline__ uint32_t smem_u32(const void* p) {
    uint32_t a;
    asm("{ .reg .u64 t; cvta.to.shared.u64 t, %1; cvt.u32.u64 %0, t; }" : "=r"(a) : "l"(p));
    return a;
}
__device__ __forceinline__ uint32_t rna_tf32(float v) {
    uint32_t r; asm("cvt.rna.tf32.f32 %0, %1;" : "=r"(r) : "f"(v)); return r;
}
__device__ __forceinline__ void cpa16(uint32_t dst, const void* src) {
    asm volatile("cp.async.cg.shared.global [%0], [%1], 16;" :: "r"(dst), "l"(src));
}
#define CP_COMMIT() asm volatile("cp.async.commit_group;")
#define CP_WAIT1()  asm volatile("cp.async.wait_group 1;" ::: "memory")

__device__ __forceinline__ void mma8(float* d, const uint32_t* a, const uint32_t* b) {
    asm volatile(
        "mma.sync.aligned.m16n8k8.row.col.f32.tf32.tf32.f32 "
        "{%0,%1,%2,%3}, {%4,%5,%6,%7}, {%8,%9}, {%0,%1,%2,%3};"
        : "+f"(d[0]), "+f"(d[1]), "+f"(d[2]), "+f"(d[3])
        : "r"(a[0]), "r"(a[1]), "r"(a[2]), "r"(a[3]), "r"(b[0]), "r"(b[1]));
}

// ---------------- prep kernels ----------------
__global__ void zero_xT_kernel() {
    size_t i = (size_t)blockIdx.x * blockDim.x + threadIdx.x;
    size_t n4 = (size_t)ZP * YP * XPD * ICN / 4;
    if (i < n4) ((float4*)g_xT)[i] = make_float4(0.f, 0.f, 0.f, 0.f);
}

__global__ void prep_x_kernel(const float* __restrict__ xin) {
    __shared__ float ts[64 * 129];
    const int tid = threadIdx.x;
    const int z = blockIdx.y, y = blockIdx.x;
    for (int i = tid; i < 2048; i += 256) {          // 64 ic x 32 float4
        int ic = i >> 5, xq = i & 31;
        float4 v = ((const float4*)xin)[(((size_t)ic * 17 + z) * 128 + y) * 32 + xq];
        ts[ic * 129 + xq * 4 + 0] = __uint_as_float(rna_tf32(v.x));
        ts[ic * 129 + xq * 4 + 1] = __uint_as_float(rna_tf32(v.y));
        ts[ic * 129 + xq * 4 + 2] = __uint_as_float(rna_tf32(v.z));
        ts[ic * 129 + xq * 4 + 3] = __uint_as_float(rna_tf32(v.w));
    }
    __syncthreads();
    size_t obase = (((size_t)(z + 1) * YP + (y + 1)) * XPD + 1) * ICN;
    for (int i = tid; i < 2048; i += 256) {          // 128 x  x 16 ic-quads
        int xx = i >> 4, icq = i & 15;
        float4 w = make_float4(ts[(icq * 4 + 0) * 129 + xx], ts[(icq * 4 + 1) * 129 + xx],
                               ts[(icq * 4 + 2) * 129 + xx], ts[(icq * 4 + 3) * 129 + xx]);
        ((float4*)(g_xT + obase + (size_t)xx * ICN))[icq] = w;
    }
}

__global__ void prep_w_kernel(const float* __restrict__ win) {
    const int oc = blockIdx.x;
    for (int i = threadIdx.x; i < 64 * 27; i += 256) {
        int ic = i / 27, tap = i % 27;
        g_Wt[((size_t)tap * NOC + oc) * ICN + ic] =
            __uint_as_float(rna_tf32(win[(size_t)oc * 1728 + i]));
    }
}

// ---------------- main MMA kernel ----------------
// CTA: M=128 pixels (one (z,y) row), N=128 oc (half), 256 thr = 8 warps (4M x 2N).
// 54 K-stages = 18 A-slabs (kz,ky,half) x 3 kx (A slab reused via row shift).
__global__ void __launch_bounds__(256, 2)
upsmpl_mma_kernel(const float* __restrict__ xin, const float* __restrict__ bin,
                  float* __restrict__ outp)
{
    extern __shared__ float sm[];
    const int tid  = threadIdx.x;
    const int lane = tid & 31, wid = tid >> 5;
    const int g = lane >> 2, tig = lane & 3;
    const int wm = wid & 3, wn = wid >> 2;

    const int y  = blockIdx.x;          // 0..127
    const int z  = blockIdx.y;          // 0..16
    const int ocbase = blockIdx.z * 128;

    const uint32_t sA = smem_u32(sm);
    const uint32_t sB = sA + 3u * ABUF * 4u;

    auto loadA = [&](int s) {           // slab s = (kz*3+ky)*2 + half
        const int kz = s / 6, ky = (s / 2) % 3, half = s & 1;
        const float* src = g_xT + ((size_t)(z + kz) * YP + (y + ky)) * XPD * ICN + half * 32;
        const uint32_t dst = sA + (uint32_t)(s % 3) * ABUF * 4u;
        for (int i = tid; i < 1040; i += 256) {     // 130 rows x 8 x 16B
            int r = i >> 3, c = i & 7;
            cpa16(dst + (uint32_t)(r * APITCH * 4 + c * 16),
                  (const char*)(src + (size_t)r * ICN) + c * 16);
        }
    };
    auto loadB = [&](int j) {           // stage j: slab j/3, kx j%3
        const int s = j / 3, kx = j % 3;
        const int kz = s / 6, ky = (s / 2) % 3, half = s & 1;
        const int tap = (kz * 3 + ky) * 3 + kx;
        const float* src = g_Wt + ((size_t)tap * NOC + ocbase) * ICN + half * 32;
        const uint32_t dst = sB + (uint32_t)(j % 3) * BBUF * 4u;
        for (int i = tid; i < 1024; i += 256) {     // 128 rows x 8 x 16B
            int r = i >> 3, c = i & 7;
            cpa16(dst + (uint32_t)(r * BPITCH * 4 + c * 16),
                  (const char*)(src + (size_t)r * ICN) + c * 16);
        }
    };

    float d[2][8][4];
    #pragma unroll
    for (int mf = 0; mf < 2; ++mf)
        #pragma unroll
        for (int f = 0; f < 8; ++f)
            #pragma unroll
            for (int r = 0; r < 4; ++r) d[mf][f][r] = 0.f;

    loadA(0); loadB(0); CP_COMMIT();
    loadA(1); loadB(1); CP_COMMIT();

    for (int j = 0; j < 54; ++j) {
        CP_WAIT1();
        __syncthreads();

        const float* Ab = sm + (size_t)((j / 3) % 3) * ABUF;
        const float* Bb = sm + 3 * ABUF + (size_t)(j % 3) * BBUF;
        const int kx = j - (j / 3) * 3;
        const int ar = kx + wm * 32 + g;
        const int br = wn * 64 + g;

        #pragma unroll
        for (int c = 0; c < 4; ++c) {
            const int col = c * 8 + tig;
            uint32_t a[2][4], b[8][2];
            #pragma unroll
            for (int mf = 0; mf < 2; ++mf) {
                const float* p = Ab + (ar + mf * 16) * APITCH + col;
                a[mf][0] = __float_as_uint(p[0]);
                a[mf][1] = __float_as_uint(p[8 * APITCH]);
                a[mf][2] = __float_as_uint(p[4]);
                a[mf][3] = __float_as_uint(p[8 * APITCH + 4]);
            }
            #pragma unroll
            for (int f = 0; f < 8; ++f) {
                const float* p = Bb + (br + f * 8) * BPITCH + col;
                b[f][0] = __float_as_uint(p[0]);
                b[f][1] = __float_as_uint(p[4]);
            }
            #pragma unroll
            for (int mf = 0; mf < 2; ++mf)
                #pragma unroll
                for (int f = 0; f < 8; ++f)
                    mma8(d[mf][f], a[mf], b[f]);
        }
        __syncthreads();                 // all reads of recycled bufs done

        if (j + 2 < 54) loadB(j + 2);
        if ((j + 2) % 3 == 1) {          // A slab s2 committed in group 3*s2-2
            int s2 = (j + 4) / 3;
            if (s2 < 18) loadA(s2);
        }
        CP_COMMIT();                     // one group per iteration (may be empty)
    }

    // ---------------- epilogue: bias + shuffle scatter + skip ----------------
    #pragma unroll
    for (int mf = 0; mf < 2; ++mf) {
        #pragma unroll
        for (int rh = 0; rh < 2; ++rh) {
            const int x = wm * 32 + mf * 16 + rh * 8 + g;
            if (z == 0) {
                #pragma unroll
                for (int f = 0; f < 4; ++f) {       // f>=4 -> oc&32 -> discarded
                    #pragma unroll
                    for (int par = 0; par < 2; ++par) {
                        const int oc = ocbase + wn * 64 + f * 8 + 2 * tig + par;
                        const int q = (oc >> 6) & 1, p = oc >> 7, nn = oc & 31;
                        const int sic = (p * 64 + q * 32 + nn) >> 1;
                        const float v = d[mf][f][rh * 2 + par] + bin[oc]
                                      + xin[(size_t)sic * 17 * 16384 + (size_t)y * 128 + x];
                        outp[((size_t)nn * 33 * 256 + (2 * y + p)) * 256 + 2 * x + q] = v;
                    }
                }
            } else {
                #pragma unroll
                for (int f = 0; f < 4; ++f) {
                    #pragma unroll
                    for (int par = 0; par < 2; ++par) {
                        const int oc0 = ocbase + wn * 64 + f * 8 + 2 * tig + par;
                        const int oc1 = oc0 + 32;   // q=1 partner
                        const float v0 = d[mf][f][rh * 2 + par] + bin[oc0]
                            + xin[((size_t)(oc0 >> 2) * 17 + z) * 16384 + (size_t)y * 128 + x];
                        const float v1 = d[mf][f + 4][rh * 2 + par] + bin[oc1]
                            + xin[((size_t)(oc1 >> 2) * 17 + z) * 16384 + (size_t)y * 128 + x];
                        const int nn = oc0 & 31, p = (oc0 >> 6) & 1, a = oc0 >> 7;
                        const size_t o = (((size_t)nn * 33 + (2 * z - 1 + a)) * 256
                                          + (2 * y + p)) * 256 + 2 * x;
                        *(float2*)(outp + o) = make_float2(v0, v1);
                    }
                }
            }
        }
    }
}

extern "C" void kernel_launch(void* const* d_in, const int* in_sizes, int n_in,
                              void* d_out, int out_size) {
    const float* x = (const float*)d_in[0];
    const float* W = (const float*)d_in[1];
    const float* b = (const float*)d_in[2];
    float* out = (float*)d_out;

    cudaFuncSetAttribute(upsmpl_mma_kernel,
                         cudaFuncAttributeMaxDynamicSharedMemorySize, SMEM_BYTES);

    size_t n4 = (size_t)ZP * YP * XPD * ICN / 4;
    zero_xT_kernel<<<(unsigned)((n4 + 255) / 256), 256>>>();
    prep_x_kernel<<<dim3(128, 17), 256>>>(x);
    prep_w_kernel<<<256, 256>>>(W);
    upsmpl_mma_kernel<<<dim3(128, 17, 2), 256, SMEM_BYTES>>>(x, b, out);
}